// round 1
// baseline (speedup 1.0000x reference)
#include <cuda_runtime.h>
#include <math.h>

// Problem constants
#define DDIM   512
#define NSEQ   2048
#define BATCH  8

// Tiling
#define BM 128
#define BN 128
#define BK 8
#define TM 8
#define TN 8
#define NTHREADS 256
#define SMEM_LD 132   // 128 + 4 pad, conflict-free transposed stores

// Scratch (device globals: no allocation allowed in kernel_launch)
__device__ float g_M[DDIM * DDIM];                         // W1 @ W2^T   (1 MB)
__device__ float g_T[BATCH * NSEQ * DDIM];                 // E @ M       (32 MB)
__device__ float g_partial[BATCH * (NSEQ / BM) * NSEQ];    // per-ntile colsums (1 MB)
__device__ float g_rcolsum[BATCH * NSEQ];                  // 1/colsum    (64 KB)

// ---------------------------------------------------------------------------
// C = A * B^T   (A: [M,K=512] row-major, B: [N,K=512] row-major), batched.
// EPI: C = exp(scale * A B^T), plus deterministic per-(block-row, column)
//      partial sums into g_partial[b][blockIdx.y][m].
// ---------------------------------------------------------------------------
template <bool EPI>
__global__ void __launch_bounds__(NTHREADS)
sgemm_nt(const float* __restrict__ A, const float* __restrict__ B,
         float* __restrict__ C, int ldc,
         long strideA, long strideB, long strideC, float scale)
{
    __shared__ float As[BK][SMEM_LD];
    __shared__ float Bs[BK][SMEM_LD];
    __shared__ float red[NTHREADS / 16][BN];   // only used when EPI

    const int b = blockIdx.z;
    const float* Ab = A + (long)b * strideA + (long)blockIdx.y * BM * DDIM;
    const float* Bb = B + (long)b * strideB + (long)blockIdx.x * BN * DDIM;
    float* Cb = C + (long)b * strideC;

    const int t  = threadIdx.x;
    const int tx = t & 15;        // 0..15 -> column groups of 8
    const int ty = t >> 4;        // 0..15 -> row groups of 8

    const int lrow = t >> 1;      // 0..127
    const int lk   = (t & 1) * 4; // 0 or 4

    float acc[TM][TN];
#pragma unroll
    for (int i = 0; i < TM; i++)
#pragma unroll
        for (int j = 0; j < TN; j++) acc[i][j] = 0.0f;

    for (int k0 = 0; k0 < DDIM; k0 += BK) {
        float4 av = *(const float4*)(Ab + (long)lrow * DDIM + k0 + lk);
        float4 bv = *(const float4*)(Bb + (long)lrow * DDIM + k0 + lk);
        __syncthreads();
        As[lk + 0][lrow] = av.x; As[lk + 1][lrow] = av.y;
        As[lk + 2][lrow] = av.z; As[lk + 3][lrow] = av.w;
        Bs[lk + 0][lrow] = bv.x; Bs[lk + 1][lrow] = bv.y;
        Bs[lk + 2][lrow] = bv.z; Bs[lk + 3][lrow] = bv.w;
        __syncthreads();

#pragma unroll
        for (int k = 0; k < BK; k++) {
            float4 a0 = *(const float4*)&As[k][ty * TM];
            float4 a1 = *(const float4*)&As[k][ty * TM + 4];
            float4 b0 = *(const float4*)&Bs[k][tx * TN];
            float4 b1 = *(const float4*)&Bs[k][tx * TN + 4];
            float ar[TM] = {a0.x, a0.y, a0.z, a0.w, a1.x, a1.y, a1.z, a1.w};
            float br[TN] = {b0.x, b0.y, b0.z, b0.w, b1.x, b1.y, b1.z, b1.w};
#pragma unroll
            for (int i = 0; i < TM; i++)
#pragma unroll
                for (int j = 0; j < TN; j++)
                    acc[i][j] = fmaf(ar[i], br[j], acc[i][j]);
        }
    }

    const int row0 = blockIdx.y * BM + ty * TM;
    const int col0 = blockIdx.x * BN + tx * TN;

    if (EPI) {
        // P = exp(scale * S); store + per-thread column partials
        float cs[TN];
#pragma unroll
        for (int j = 0; j < TN; j++) cs[j] = 0.0f;
#pragma unroll
        for (int i = 0; i < TM; i++) {
#pragma unroll
            for (int j = 0; j < TN; j++) {
                float p = __expf(acc[i][j] * scale);
                acc[i][j] = p;
                cs[j] += p;
            }
            float4* dst = (float4*)(Cb + (long)(row0 + i) * ldc + col0);
            dst[0] = make_float4(acc[i][0], acc[i][1], acc[i][2], acc[i][3]);
            dst[1] = make_float4(acc[i][4], acc[i][5], acc[i][6], acc[i][7]);
        }
#pragma unroll
        for (int j = 0; j < TN; j++) red[ty][tx * TN + j] = cs[j];
        __syncthreads();
        if (t < BN) {
            float s = 0.0f;
#pragma unroll
            for (int r = 0; r < 16; r++) s += red[r][t];
            g_partial[((long)b * (NSEQ / BM) + blockIdx.y) * NSEQ
                      + blockIdx.x * BN + t] = s;
        }
    } else {
#pragma unroll
        for (int i = 0; i < TM; i++) {
            float4* dst = (float4*)(Cb + (long)(row0 + i) * ldc + col0);
            dst[0] = make_float4(acc[i][0], acc[i][1], acc[i][2], acc[i][3]);
            dst[1] = make_float4(acc[i][4], acc[i][5], acc[i][6], acc[i][7]);
        }
    }
}

// ---------------------------------------------------------------------------
// C = A * B   (A: [M,K=512] row-major, B: [K=512,N] row-major). T = E @ M.
// ---------------------------------------------------------------------------
__global__ void __launch_bounds__(NTHREADS)
sgemm_nn(const float* __restrict__ A, const float* __restrict__ B,
         float* __restrict__ C)
{
    __shared__ float As[BK][SMEM_LD];
    __shared__ float Bs[BK][SMEM_LD];

    const float* Ab = A + (long)blockIdx.y * BM * DDIM;
    const float* Bb = B + blockIdx.x * BN;

    const int t  = threadIdx.x;
    const int tx = t & 15;
    const int ty = t >> 4;

    const int lrow = t >> 1;
    const int lk   = (t & 1) * 4;
    const int bk   = t >> 5;        // 0..7
    const int bcol = (t & 31) * 4;  // 0..124

    float acc[TM][TN];
#pragma unroll
    for (int i = 0; i < TM; i++)
#pragma unroll
        for (int j = 0; j < TN; j++) acc[i][j] = 0.0f;

    for (int k0 = 0; k0 < DDIM; k0 += BK) {
        float4 av = *(const float4*)(Ab + (long)lrow * DDIM + k0 + lk);
        float4 bv = *(const float4*)(Bb + (long)(k0 + bk) * DDIM + bcol);
        __syncthreads();
        As[lk + 0][lrow] = av.x; As[lk + 1][lrow] = av.y;
        As[lk + 2][lrow] = av.z; As[lk + 3][lrow] = av.w;
        *(float4*)&Bs[bk][bcol] = bv;
        __syncthreads();

#pragma unroll
        for (int k = 0; k < BK; k++) {
            float4 a0 = *(const float4*)&As[k][ty * TM];
            float4 a1 = *(const float4*)&As[k][ty * TM + 4];
            float4 b0 = *(const float4*)&Bs[k][tx * TN];
            float4 b1 = *(const float4*)&Bs[k][tx * TN + 4];
            float ar[TM] = {a0.x, a0.y, a0.z, a0.w, a1.x, a1.y, a1.z, a1.w};
            float br[TN] = {b0.x, b0.y, b0.z, b0.w, b1.x, b1.y, b1.z, b1.w};
#pragma unroll
            for (int i = 0; i < TM; i++)
#pragma unroll
                for (int j = 0; j < TN; j++)
                    acc[i][j] = fmaf(ar[i], br[j], acc[i][j]);
        }
    }

    const int row0 = blockIdx.y * BM + ty * TM;
    const int col0 = blockIdx.x * BN + tx * TN;
#pragma unroll
    for (int i = 0; i < TM; i++) {
        float4* dst = (float4*)(C + (long)(row0 + i) * DDIM + col0);
        dst[0] = make_float4(acc[i][0], acc[i][1], acc[i][2], acc[i][3]);
        dst[1] = make_float4(acc[i][4], acc[i][5], acc[i][6], acc[i][7]);
    }
}

// ---------------------------------------------------------------------------
// 1/colsum[b,m] = 1 / sum over the 16 n-tiles of g_partial
// ---------------------------------------------------------------------------
__global__ void colsum_reduce_kernel()
{
    int idx = blockIdx.x * blockDim.x + threadIdx.x;   // b*NSEQ + m
    if (idx >= BATCH * NSEQ) return;
    int b = idx / NSEQ;
    int m = idx - b * NSEQ;
    float s = 0.0f;
#pragma unroll
    for (int t = 0; t < NSEQ / BM; t++)
        s += g_partial[((long)b * (NSEQ / BM) + t) * NSEQ + m];
    g_rcolsum[idx] = 1.0f / s;
}

// ---------------------------------------------------------------------------
// out[b,n,m] *= 1/colsum[b,m]   (float4 per thread)
// ---------------------------------------------------------------------------
__global__ void normalize_kernel(float* __restrict__ out)
{
    long i = (long)blockIdx.x * blockDim.x + threadIdx.x;  // float4 index
    const long total4 = (long)BATCH * NSEQ * NSEQ / 4;
    if (i >= total4) return;
    long e = i * 4;
    int m = (int)(e & (NSEQ - 1));
    long bn = e >> 11;              // e / NSEQ
    int b = (int)(bn >> 11);        // bn / NSEQ
    const float* rc = g_rcolsum + b * NSEQ + m;
    float4 v = ((float4*)out)[i];
    v.x *= rc[0]; v.y *= rc[1]; v.z *= rc[2]; v.w *= rc[3];
    ((float4*)out)[i] = v;
}

// ---------------------------------------------------------------------------
extern "C" void kernel_launch(void* const* d_in, const int* in_sizes, int n_in,
                              void* d_out, int out_size)
{
    const float* E  = (const float*)d_in[0];   // [8,2048,512]
    const float* W1 = (const float*)d_in[1];   // [512,512]
    const float* W2 = (const float*)d_in[2];   // [512,512]
    float* out = (float*)d_out;                // [8,2048,2048]

    float* gM; cudaGetSymbolAddress((void**)&gM, g_M);
    float* gT; cudaGetSymbolAddress((void**)&gT, g_T);

    const float scale = 0.044194173824159216f; // 1/sqrt(512)

    // 1) M = W1 @ W2^T   [512,512]
    {
        dim3 grid(DDIM / BN, DDIM / BM, 1);
        sgemm_nt<false><<<grid, NTHREADS>>>(W1, W2, gM, DDIM, 0, 0, 0, 1.0f);
    }
    // 2) T = E @ M       [B*N, 512]
    {
        dim3 grid(DDIM / BN, (BATCH * NSEQ) / BM, 1);
        sgemm_nn<<<grid, NTHREADS>>>(E, gM, gT);
    }
    // 3) P = exp(scale * T E^T) per batch, with column partial sums
    {
        dim3 grid(NSEQ / BN, NSEQ / BM, BATCH);
        sgemm_nt<true><<<grid, NTHREADS>>>(
            gT, E, out, NSEQ,
            (long)NSEQ * DDIM, (long)NSEQ * DDIM, (long)NSEQ * NSEQ, scale);
    }
    // 4) reciprocal column sums
    {
        int n = BATCH * NSEQ;
        colsum_reduce_kernel<<<(n + 255) / 256, 256>>>();
    }
    // 5) normalize
    {
        long total4 = (long)BATCH * NSEQ * NSEQ / 4;
        normalize_kernel<<<(unsigned)((total4 + 255) / 256), 256>>>(out);
    }
}

// round 3
// speedup vs baseline: 2.6260x; 2.6260x over previous
#include <cuda_runtime.h>
#include <cuda_bf16.h>
#include <math.h>
#include <stdint.h>

#define DDIM   512
#define NSEQ   2048
#define BATCH  8
#define ROWS_ALL (BATCH * NSEQ)

#define BK       64
#define NTHREADS 256
#define TILE_B   16384              // 128 rows x 128 bytes (64 bf16)
#define STAGE_B  (4 * TILE_B)       // Ah, Al, Bh, Bl
#define SMEM_TOTAL (2 * STAGE_B)    // 128 KB double buffered

// ---------------- device scratch (no allocation allowed) -------------------
__device__ __nv_bfloat16 g_Eh[ROWS_ALL * DDIM];
__device__ __nv_bfloat16 g_El[ROWS_ALL * DDIM];
__device__ __nv_bfloat16 g_Th[ROWS_ALL * DDIM];
__device__ __nv_bfloat16 g_Tl[ROWS_ALL * DDIM];
__device__ __nv_bfloat16 g_W1h[DDIM * DDIM];
__device__ __nv_bfloat16 g_W1l[DDIM * DDIM];
__device__ __nv_bfloat16 g_W2h[DDIM * DDIM];
__device__ __nv_bfloat16 g_W2l[DDIM * DDIM];
__device__ __nv_bfloat16 g_Mth[DDIM * DDIM];
__device__ __nv_bfloat16 g_Mtl[DDIM * DDIM];
__device__ float g_partial[BATCH * 16 * NSEQ];
__device__ float g_rcolsum[BATCH * NSEQ];

// ---------------- PTX helpers (base PTX only: sm_80 class) -----------------
__device__ __forceinline__ uint32_t smem_u32(const void* p) {
    uint32_t a;
    asm("{ .reg .u64 t; cvta.to.shared.u64 t, %1; cvt.u32.u64 %0, t; }"
        : "=r"(a) : "l"(p));
    return a;
}
__device__ __forceinline__ void cp_async16(uint32_t dst, const void* src) {
    asm volatile("cp.async.cg.shared.global [%0], [%1], 16;" :: "r"(dst), "l"(src));
}
__device__ __forceinline__ void cp_commit() {
    asm volatile("cp.async.commit_group;");
}
__device__ __forceinline__ void cp_wait1() {
    asm volatile("cp.async.wait_group 1;");
}
__device__ __forceinline__ void cp_wait0() {
    asm volatile("cp.async.wait_group 0;");
}
__device__ __forceinline__ void ldm_x4(uint32_t* r, uint32_t addr) {
    asm volatile("ldmatrix.sync.aligned.m8n8.x4.shared.b16 {%0,%1,%2,%3}, [%4];"
                 : "=r"(r[0]), "=r"(r[1]), "=r"(r[2]), "=r"(r[3]) : "r"(addr));
}
__device__ __forceinline__ void mma16816(float* d, const uint32_t* a, const uint32_t* b) {
    asm volatile(
        "mma.sync.aligned.m16n8k16.row.col.f32.bf16.bf16.f32 "
        "{%0,%1,%2,%3}, {%4,%5,%6,%7}, {%8,%9}, {%0,%1,%2,%3};"
        : "+f"(d[0]), "+f"(d[1]), "+f"(d[2]), "+f"(d[3])
        : "r"(a[0]), "r"(a[1]), "r"(a[2]), "r"(a[3]), "r"(b[0]), "r"(b[1]));
}
__device__ __forceinline__ uint32_t pack2_hi(float x, float y) {
    __nv_bfloat162 v = __floats2bfloat162_rn(x, y);
    return *(uint32_t*)&v;
}

// ---------------------------------------------------------------------------
// split fp32 -> bf16 hi + bf16 lo
// ---------------------------------------------------------------------------
__global__ void split_kernel(const float4* __restrict__ x,
                             uint2* __restrict__ h, uint2* __restrict__ l, int n4)
{
    int i = blockIdx.x * blockDim.x + threadIdx.x;
    if (i >= n4) return;
    float4 v = x[i];
    __nv_bfloat16 h0 = __float2bfloat16(v.x);
    __nv_bfloat16 h1 = __float2bfloat16(v.y);
    __nv_bfloat16 h2 = __float2bfloat16(v.z);
    __nv_bfloat16 h3 = __float2bfloat16(v.w);
    float r0 = v.x - __bfloat162float(h0);
    float r1 = v.y - __bfloat162float(h1);
    float r2 = v.z - __bfloat162float(h2);
    float r3 = v.w - __bfloat162float(h3);
    uint2 hv, lv;
    hv.x = pack2_hi(__bfloat162float(h0), __bfloat162float(h1));
    hv.y = pack2_hi(__bfloat162float(h2), __bfloat162float(h3));
    lv.x = pack2_hi(r0, r1);
    lv.y = pack2_hi(r2, r3);
    h[i] = hv;
    l[i] = lv;
}

// ---------------------------------------------------------------------------
// nt-GEMM on tensor cores (mma.sync bf16), split-bf16 3-term emulation.
// D[i,j] = sum_k (Ah+Al)[i,k]*(Bh+Bl)[j,k]  (AlBl dropped)
// A rows at blockIdx.y*128, B rows at blockIdx.x*128, K=512, batched over z.
// EPI=0: re-split D into bf16 hi/lo -> Ch_, Cl_ (ldc elems)
// EPI=1: C_ = exp(scale*D), plus per-tile column sums -> g_partial
// ---------------------------------------------------------------------------
template <int EPI>
__global__ void __launch_bounds__(NTHREADS, 1)
mma_gemm(const __nv_bfloat16* __restrict__ Ah_, const __nv_bfloat16* __restrict__ Al_,
         const __nv_bfloat16* __restrict__ Bh_, const __nv_bfloat16* __restrict__ Bl_,
         float* __restrict__ C_, __nv_bfloat16* __restrict__ Ch_,
         __nv_bfloat16* __restrict__ Cl_, int ldc,
         long sA, long sB, long sC, float scale)
{
    extern __shared__ char smem[];
    const uint32_t sb = smem_u32(smem);
    const int t    = threadIdx.x;
    const int lane = t & 31;
    const int wid  = t >> 5;
    const int warp_m = wid & 3;     // 0..3 -> 32-row slab
    const int warp_n = wid >> 2;    // 0..1 -> 64-col slab
    const int bz = blockIdx.z;

    const __nv_bfloat16* Ah = Ah_ + bz * sA + (long)blockIdx.y * 128 * DDIM;
    const __nv_bfloat16* Al = Al_ + bz * sA + (long)blockIdx.y * 128 * DDIM;
    const __nv_bfloat16* Bh = Bh_ + bz * sB + (long)blockIdx.x * 128 * DDIM;
    const __nv_bfloat16* Bl = Bl_ + bz * sB + (long)blockIdx.x * 128 * DDIM;

    // per-thread load slots: idx = t + 256*i -> row = idx>>3, 16B chunk = idx&7
    const int lr0 = t >> 3;        // base row (advances by 32 per i)
    const int lc  = t & 7;

    float acc[2][8][4];
#pragma unroll
    for (int im = 0; im < 2; im++)
#pragma unroll
        for (int nt = 0; nt < 8; nt++)
#pragma unroll
            for (int j = 0; j < 4; j++) acc[im][nt][j] = 0.0f;

    auto load_stage = [&](int s, int k0) {
        const uint32_t dstb = sb + s * STAGE_B;
#pragma unroll
        for (int i = 0; i < 4; i++) {
            const int r = lr0 + 32 * i;
            uint32_t off = r * 128 + lc * 16;
            off ^= (off >> 3) & 0x70;                      // SW128 swizzle
            const long go = (long)r * DDIM + k0 + lc * 8;
            cp_async16(dstb + off,              Ah + go);
            cp_async16(dstb + TILE_B + off,     Al + go);
            cp_async16(dstb + 2 * TILE_B + off, Bh + go);
            cp_async16(dstb + 3 * TILE_B + off, Bl + go);
        }
        cp_commit();
    };

    load_stage(0, 0);
    load_stage(1, BK);

    const int mi  = lane >> 3;      // ldmatrix sub-matrix id
    const int lr8 = lane & 7;

    for (int it = 0; it < 8; ++it) {
        if (it == 7) cp_wait0(); else cp_wait1();
        __syncthreads();

        const uint32_t ab_h = sb + (it & 1) * STAGE_B;
        const uint32_t ab_l = ab_h + TILE_B;
        const uint32_t bb_h = ab_h + 2 * TILE_B;
        const uint32_t bb_l = ab_h + 3 * TILE_B;

#pragma unroll
        for (int ks = 0; ks < 4; ks++) {
            const int kb = ks * 32;  // byte offset of this k16 slice

            uint32_t ah[2][4], al[2][4];
#pragma unroll
            for (int im = 0; im < 2; im++) {
                const int row = warp_m * 32 + im * 16 + ((mi & 1) << 3) + lr8;
                uint32_t off = row * 128 + kb + ((mi >> 1) << 4);
                off ^= (off >> 3) & 0x70;
                ldm_x4(ah[im], ab_h + off);
                ldm_x4(al[im], ab_l + off);
            }

            uint32_t bh[8][2], bl[8][2];
#pragma unroll
            for (int bt = 0; bt < 4; bt++) {    // each x4 = two n8 tiles
                const int row = warp_n * 64 + bt * 16 + ((mi >> 1) << 3) + lr8;
                uint32_t off = row * 128 + kb + ((mi & 1) << 4);
                off ^= (off >> 3) & 0x70;
                uint32_t r4[4];
                ldm_x4(r4, bb_h + off);
                bh[2 * bt][0] = r4[0]; bh[2 * bt][1] = r4[1];
                bh[2 * bt + 1][0] = r4[2]; bh[2 * bt + 1][1] = r4[3];
                ldm_x4(r4, bb_l + off);
                bl[2 * bt][0] = r4[0]; bl[2 * bt][1] = r4[1];
                bl[2 * bt + 1][0] = r4[2]; bl[2 * bt + 1][1] = r4[3];
            }

#pragma unroll
            for (int im = 0; im < 2; im++)
#pragma unroll
                for (int nt = 0; nt < 8; nt++) {
                    mma16816(acc[im][nt], ah[im], bh[nt]);
                    mma16816(acc[im][nt], ah[im], bl[nt]);
                    mma16816(acc[im][nt], al[im], bh[nt]);
                }
        }
        __syncthreads();
        if (it < 6) load_stage(it & 1, (it + 2) * BK);
    }

    // -------------------- epilogue --------------------
    const int g  = lane >> 2;
    const int tg = lane & 3;
    const int row_base = blockIdx.y * 128 + warp_m * 32;
    const int col_base = blockIdx.x * 128 + warp_n * 64;

    if (EPI == 1) {
        float* C = C_ + bz * sC;
        float colsum[8][2];
#pragma unroll
        for (int nt = 0; nt < 8; nt++) { colsum[nt][0] = 0.f; colsum[nt][1] = 0.f; }

#pragma unroll
        for (int im = 0; im < 2; im++)
#pragma unroll
            for (int nt = 0; nt < 8; nt++) {
                float e0 = __expf(acc[im][nt][0] * scale);
                float e1 = __expf(acc[im][nt][1] * scale);
                float e2 = __expf(acc[im][nt][2] * scale);
                float e3 = __expf(acc[im][nt][3] * scale);
                colsum[nt][0] += e0 + e2;
                colsum[nt][1] += e1 + e3;
                const int r0 = row_base + im * 16 + g;
                const int col = col_base + nt * 8 + 2 * tg;
                *(float2*)(C + (long)r0 * ldc + col)       = make_float2(e0, e1);
                *(float2*)(C + (long)(r0 + 8) * ldc + col) = make_float2(e2, e3);
            }
        // reduce over g (lanes differing in bits 2..4)
#pragma unroll
        for (int nt = 0; nt < 8; nt++)
#pragma unroll
            for (int j = 0; j < 2; j++) {
                float v = colsum[nt][j];
                v += __shfl_xor_sync(0xFFFFFFFFu, v, 4);
                v += __shfl_xor_sync(0xFFFFFFFFu, v, 8);
                v += __shfl_xor_sync(0xFFFFFFFFu, v, 16);
                colsum[nt][j] = v;
            }
        float* red = (float*)smem;      // [4][128]
        __syncthreads();
        if (lane < 4) {
#pragma unroll
            for (int nt = 0; nt < 8; nt++) {
                red[warp_m * 128 + warp_n * 64 + nt * 8 + 2 * lane]     = colsum[nt][0];
                red[warp_m * 128 + warp_n * 64 + nt * 8 + 2 * lane + 1] = colsum[nt][1];
            }
        }
        __syncthreads();
        if (t < 128) {
            float s = red[t] + red[128 + t] + red[256 + t] + red[384 + t];
            g_partial[((long)bz * 16 + blockIdx.y) * NSEQ + blockIdx.x * 128 + t] = s;
        }
    } else {
#pragma unroll
        for (int im = 0; im < 2; im++)
#pragma unroll
            for (int nt = 0; nt < 8; nt++) {
                const int r0 = row_base + im * 16 + g;
                const int col = col_base + nt * 8 + 2 * tg;
#pragma unroll
                for (int h = 0; h < 2; h++) {       // row g, row g+8
                    float x = acc[im][nt][2 * h];
                    float y = acc[im][nt][2 * h + 1];
                    __nv_bfloat16 xh = __float2bfloat16(x);
                    __nv_bfloat16 yh = __float2bfloat16(y);
                    uint32_t hi = pack2_hi(__bfloat162float(xh), __bfloat162float(yh));
                    uint32_t lo = pack2_hi(x - __bfloat162float(xh), y - __bfloat162float(yh));
                    const long off = (long)(r0 + 8 * h) * ldc + col;
                    *(uint32_t*)(Ch_ + off) = hi;
                    *(uint32_t*)(Cl_ + off) = lo;
                }
            }
    }
}

// ---------------------------------------------------------------------------
__global__ void colsum_reduce_kernel()
{
    int idx = blockIdx.x * blockDim.x + threadIdx.x;
    if (idx >= BATCH * NSEQ) return;
    int b = idx / NSEQ;
    int m = idx - b * NSEQ;
    float s = 0.0f;
#pragma unroll
    for (int t = 0; t < 16; t++)
        s += g_partial[((long)b * 16 + t) * NSEQ + m];
    g_rcolsum[idx] = 1.0f / s;
}

__global__ void normalize_kernel(float* __restrict__ out)
{
    long i = (long)blockIdx.x * blockDim.x + threadIdx.x;
    const long total4 = (long)BATCH * NSEQ * NSEQ / 4;
    if (i >= total4) return;
    long e = i * 4;
    int m = (int)(e & (NSEQ - 1));
    long bn = e >> 11;
    int b = (int)(bn >> 11);
    const float* rc = g_rcolsum + b * NSEQ + m;
    float4 v = ((float4*)out)[i];
    v.x *= rc[0]; v.y *= rc[1]; v.z *= rc[2]; v.w *= rc[3];
    ((float4*)out)[i] = v;
}

// ---------------------------------------------------------------------------
extern "C" void kernel_launch(void* const* d_in, const int* in_sizes, int n_in,
                              void* d_out, int out_size)
{
    const float* E  = (const float*)d_in[0];   // [8,2048,512]
    const float* W1 = (const float*)d_in[1];   // [512,512]
    const float* W2 = (const float*)d_in[2];   // [512,512]
    float* out = (float*)d_out;                // [8,2048,2048]

    __nv_bfloat16 *eh, *el, *th, *tl, *w1h, *w1l, *w2h, *w2l, *mth, *mtl;
    cudaGetSymbolAddress((void**)&eh,  g_Eh);
    cudaGetSymbolAddress((void**)&el,  g_El);
    cudaGetSymbolAddress((void**)&th,  g_Th);
    cudaGetSymbolAddress((void**)&tl,  g_Tl);
    cudaGetSymbolAddress((void**)&w1h, g_W1h);
    cudaGetSymbolAddress((void**)&w1l, g_W1l);
    cudaGetSymbolAddress((void**)&w2h, g_W2h);
    cudaGetSymbolAddress((void**)&w2l, g_W2l);
    cudaGetSymbolAddress((void**)&mth, g_Mth);
    cudaGetSymbolAddress((void**)&mtl, g_Mtl);

    cudaFuncSetAttribute(mma_gemm<0>, cudaFuncAttributeMaxDynamicSharedMemorySize, SMEM_TOTAL);
    cudaFuncSetAttribute(mma_gemm<1>, cudaFuncAttributeMaxDynamicSharedMemorySize, SMEM_TOTAL);

    const float scale = 0.044194173824159216f;  // 1/sqrt(512)

    split_kernel<<<256, 256>>>((const float4*)W1, (uint2*)w1h, (uint2*)w1l, DDIM * DDIM / 4);
    split_kernel<<<256, 256>>>((const float4*)W2, (uint2*)w2h, (uint2*)w2l, DDIM * DDIM / 4);
    split_kernel<<<8192, 256>>>((const float4*)E, (uint2*)eh, (uint2*)el, ROWS_ALL * DDIM / 4);

    // Mt = W2 @ W1^T  (then T = E @ Mt^T = E W1 W2^T)
    mma_gemm<0><<<dim3(4, 4, 1), NTHREADS, SMEM_TOTAL>>>(
        w2h, w2l, w1h, w1l, nullptr, mth, mtl, DDIM, 0, 0, 0, 0.0f);

    // T = E @ Mt^T   [16384, 512]
    mma_gemm<0><<<dim3(4, 128, 1), NTHREADS, SMEM_TOTAL>>>(
        eh, el, mth, mtl, nullptr, th, tl, DDIM, 0, 0, 0, 0.0f);

    // P = exp(scale * T E^T) per batch + column partial sums
    mma_gemm<1><<<dim3(16, 16, 8), NTHREADS, SMEM_TOTAL>>>(
        th, tl, eh, el, out, nullptr, nullptr, NSEQ,
        (long)NSEQ * DDIM, (long)NSEQ * DDIM, (long)NSEQ * NSEQ, scale);

    colsum_reduce_kernel<<<(BATCH * NSEQ + 255) / 256, 256>>>();

    const long total4 = (long)BATCH * NSEQ * NSEQ / 4;
    normalize_kernel<<<(unsigned)((total4 + 255) / 256), 256>>>(out);
}